// round 15
// baseline (speedup 1.0000x reference)
#include <cuda_runtime.h>
#include <cuda_bf16.h>
#include <cstdint>

#define D_IN      64
#define LATENT    512
#define KSEL      32
#define CHUNK     32
#define NTHREADS  1024
#define GRID      152
#define DEC_STRIDE 64
#define ZSTRIDE   516

typedef unsigned long long ull;

// ---------------- common helpers ----------------
__device__ __forceinline__ ull pack2(float lo, float hi) {
    ull r; asm("mov.b64 %0, {%1,%2};" : "=l"(r) : "f"(lo), "f"(hi)); return r;
}
__device__ __forceinline__ void unpack2(ull v, float& lo, float& hi) {
    asm("mov.b64 {%0,%1}, %2;" : "=f"(lo), "=f"(hi) : "l"(v));
}
__device__ __forceinline__ ull fma2(ull a, ull b, ull c) {
    ull d; asm("fma.rn.f32x2 %0, %1, %2, %3;" : "=l"(d) : "l"(a), "l"(b), "l"(c)); return d;
}
__device__ __forceinline__ ull add2(ull a, ull b) {
    ull d; asm("add.rn.f32x2 %0, %1, %2;" : "=l"(d) : "l"(a), "l"(b)); return d;
}
__device__ __forceinline__ unsigned smem_u32(const void* p) {
    unsigned a; asm("{ .reg .u64 t; cvta.to.shared.u64 t, %1; cvt.u32.u64 %0, t; }" : "=r"(a) : "l"(p));
    return a;
}
__device__ __forceinline__ void cp_async8(unsigned dst, const void* src) {
    asm volatile("cp.async.ca.shared.global [%0], [%1], 8;" :: "r"(dst), "l"(src) : "memory");
}
__device__ __forceinline__ unsigned sw128(unsigned b) { return b ^ ((b >> 3) & 0x70); }
__device__ __forceinline__ unsigned short bfb(float f) {
    __nv_bfloat16 b = __float2bfloat16(f);
    return *reinterpret_cast<unsigned short*>(&b);
}
__device__ __forceinline__ float bff(float f) {
    return __bfloat162float(__float2bfloat16(f));
}
// va load with relu applied here (zsh holds pre-relu z = Wx + b)
__device__ __forceinline__ void load_va_relu(const float* __restrict__ zrow, int lane, float* va) {
    const float4* zr = reinterpret_cast<const float4*>(zrow);
    #pragma unroll
    for (int q = 0; q < 4; q++) {
        float4 t = zr[lane + 32 * q];
        va[4 * q + 0] = fmaxf(t.x, 0.0f); va[4 * q + 1] = fmaxf(t.y, 0.0f);
        va[4 * q + 2] = fmaxf(t.z, 0.0f); va[4 * q + 3] = fmaxf(t.w, 0.0f);
    }
}

// ---------------- top-k + z write + decode on preloaded va (exact, stable ties) ----------------
// (identical to the proven R12 version)
__device__ __forceinline__ void topk_rest(
    const float* va, long long row, int lane, unsigned ltmask,
    unsigned& Tprev, const float* __restrict__ decT, ull* __restrict__ zs,
    float* __restrict__ outx, float* __restrict__ outz, float db0, float db1)
{
    const unsigned FULL = 0xffffffffu;
    const unsigned lane1024 = ((unsigned)lane) << 10;

    float lmx = 0.0f;
    #pragma unroll
    for (int j = 0; j < 16; j++) lmx = fmaxf(lmx, va[j]);
    unsigned mxu = __reduce_max_sync(FULL, __float_as_uint(lmx));

    unsigned T, ge_cnt;
    if (mxu == 0u) {
        T = 0u; ge_cnt = 512u;
    } else {
        unsigned lo = 0u, hi = mxu + 1u;
        unsigned lo_c = 512u, hi_c = 1u;
        unsigned m = Tprev;
        if (m <= lo || m >= hi) m = lo + ((hi - lo) >> 1);
        T = 0u; ge_cnt = 512u;
        while (true) {
            int cgt = 0;
            #pragma unroll
            for (int j = 0; j < 16; j++) cgt += (__float_as_uint(va[j]) >= m);
            cgt = __reduce_add_sync(FULL, cgt);
            if (cgt == KSEL) {
                unsigned tmin = 0xffffffffu;
                #pragma unroll
                for (int j = 0; j < 16; j++) {
                    unsigned u = __float_as_uint(va[j]);
                    if (u >= m) tmin = min(tmin, u);
                }
                T = __reduce_min_sync(FULL, tmin);
                ge_cnt = KSEL;
                break;
            }
            if (cgt > KSEL) { lo = m; lo_c = (unsigned)cgt; }
            else            { hi = m; hi_c = (unsigned)cgt; }
            if (hi - lo <= 1u) { T = lo; ge_cnt = lo_c; break; }
            float fl = __uint_as_float(lo), fh = __uint_as_float(hi);
            float lc = __logf((float)lo_c);
            float hc = __logf((float)max(hi_c, 1u));
            float t  = (lc - 3.4657359f) / fmaxf(lc - hc, 1e-6f);
            float mf = fl + t * (fh - fl);
            unsigned mm = __float_as_uint(mf);
            if (!(mf > fl && mf < fh)) mm = lo + ((hi - lo) >> 1);
            m = mm;
            if (m <= lo) m = lo + 1u;
            if (m >= hi) m = hi - 1u;
        }
        Tprev = T;
    }

    if (ge_cnt == KSEL) {
        {
            float4* oz = reinterpret_cast<float4*>(outz + row * LATENT);
            #pragma unroll
            for (int q = 0; q < 4; q++) {
                float4 o;
                o.x = (__float_as_uint(va[4*q+0]) >= T) ? va[4*q+0] : 0.0f;
                o.y = (__float_as_uint(va[4*q+1]) >= T) ? va[4*q+1] : 0.0f;
                o.z = (__float_as_uint(va[4*q+2]) >= T) ? va[4*q+2] : 0.0f;
                o.w = (__float_as_uint(va[4*q+3]) >= T) ? va[4*q+3] : 0.0f;
                oz[lane + 32 * q] = o;
            }
        }
        unsigned running = 0;
        #pragma unroll
        for (int j = 0; j < 16; j++) {
            unsigned u = __float_as_uint(va[j]);
            bool sel = (u >= T);
            unsigned bal = __ballot_sync(FULL, sel);
            if (sel) {
                int slot = running + __popc(bal & ltmask);
                unsigned off = (unsigned)(((j >> 2) * 128 + (j & 3)) * 256) + lane1024;
                zs[slot] = ((ull)off << 32) | (ull)u;
            }
            running += __popc(bal);
        }
    } else {
        // rare tie path: exact stable ties matching jax.lax.top_k
        unsigned selmask = 0u;
        int gt = 0;
        #pragma unroll
        for (int j = 0; j < 16; j++) gt += (__float_as_uint(va[j]) > T);
        gt = __reduce_add_sync(FULL, gt);
        int need = KSEL - gt;
        int running = 0;
        #pragma unroll
        for (int j = 0; j < 16; j++) {
            unsigned u = __float_as_uint(va[j]);
            bool g = (u > T), e = (u == T);
            unsigned eb = __ballot_sync(FULL, e);
            int rank = running + __popc(eb & ltmask);
            running += __popc(eb);
            if (g || (e && rank < need)) selmask |= 1u << j;
        }
        {
            float4* oz = reinterpret_cast<float4*>(outz + row * LATENT);
            #pragma unroll
            for (int q = 0; q < 4; q++) {
                float4 o;
                o.x = ((selmask >> (4 * q + 0)) & 1u) ? va[4 * q + 0] : 0.0f;
                o.y = ((selmask >> (4 * q + 1)) & 1u) ? va[4 * q + 1] : 0.0f;
                o.z = ((selmask >> (4 * q + 2)) & 1u) ? va[4 * q + 2] : 0.0f;
                o.w = ((selmask >> (4 * q + 3)) & 1u) ? va[4 * q + 3] : 0.0f;
                oz[lane + 32 * q] = o;
            }
        }
        unsigned running2 = 0;
        #pragma unroll
        for (int j = 0; j < 16; j++) {
            bool sel = (selmask >> j) & 1u;
            unsigned bal = __ballot_sync(FULL, sel);
            if (sel) {
                int slot = running2 + __popc(bal & ltmask);
                unsigned off = (unsigned)(((j >> 2) * 128 + (j & 3)) * 256) + lane1024;
                zs[slot] = ((ull)off << 32) | (ull)__float_as_uint(va[j]);
            }
            running2 += __popc(bal);
        }
    }
    __syncwarp();

    const char* decTlane = reinterpret_cast<const char*>(decT) + 8 * lane;
    ull acc0 = pack2(db0, db1), acc1 = 0, acc2 = 0, acc3 = 0;
    #pragma unroll
    for (int s4 = 0; s4 < KSEL; s4 += 4) {
        ulonglong2 p01 = *reinterpret_cast<const ulonglong2*>(zs + s4);
        ulonglong2 p23 = *reinterpret_cast<const ulonglong2*>(zs + s4 + 2);
        {
            float v = __uint_as_float((unsigned)p01.x);
            acc0 = fma2(pack2(v, v), *reinterpret_cast<const ull*>(decTlane + (p01.x >> 32)), acc0);
        }
        {
            float v = __uint_as_float((unsigned)p01.y);
            acc1 = fma2(pack2(v, v), *reinterpret_cast<const ull*>(decTlane + (p01.y >> 32)), acc1);
        }
        {
            float v = __uint_as_float((unsigned)p23.x);
            acc2 = fma2(pack2(v, v), *reinterpret_cast<const ull*>(decTlane + (p23.x >> 32)), acc2);
        }
        {
            float v = __uint_as_float((unsigned)p23.y);
            acc3 = fma2(pack2(v, v), *reinterpret_cast<const ull*>(decTlane + (p23.y >> 32)), acc3);
        }
    }
    acc0 = add2(add2(acc0, acc1), add2(acc2, acc3));
    float o0, o1;
    unpack2(acc0, o0, o1);
    float2 ov; ov.x = o0; ov.y = o1;
    *reinterpret_cast<float2*>(outx + row * D_IN + 2 * lane) = ov;
}

// ---------------- tcgen05 helpers (only in the *a* pass) ----------------
#if defined(__CUDA_ARCH_FEAT_SM103_ALL) || defined(__CUDA_ARCH_FEAT_SM100_ALL)
#define HAVE_TCGEN05 1
#define MMA_IDESC 0x8080490u             // f32 accum, bf16 x bf16, M=128, N=32
#define DESC_BASE 0x4000404000010000ULL  // SW128 K-major, LBO=1, SBO=64, ver=1

__device__ __forceinline__ unsigned elect_one() {
    unsigned p;
    asm volatile("{ .reg .pred p; elect.sync _|p, 0xFFFFFFFF; selp.b32 %0, 1, 0, p; }" : "=r"(p));
    return p;
}
__device__ __forceinline__ void mma_ts(unsigned d_t, unsigned a_t, ull bdesc, unsigned en) {
    asm volatile(
        "{ .reg .pred p; setp.ne.u32 p, %5, 0;\n\t"
        "tcgen05.mma.cta_group::1.kind::f16 [%0], [%1], %2, %3, {%4,%4,%4,%4}, p; }"
        :: "r"(d_t), "r"(a_t), "l"(bdesc), "r"(MMA_IDESC), "r"(0u), "r"(en) : "memory");
}
__device__ __forceinline__ void sttm16(unsigned t, const unsigned* r) {
    asm volatile("tcgen05.st.sync.aligned.32x32b.x16.b32 [%0], "
        "{%1,%2,%3,%4,%5,%6,%7,%8,%9,%10,%11,%12,%13,%14,%15,%16};"
        :: "r"(t),
        "r"(r[0]),"r"(r[1]),"r"(r[2]),"r"(r[3]),"r"(r[4]),"r"(r[5]),"r"(r[6]),"r"(r[7]),
        "r"(r[8]),"r"(r[9]),"r"(r[10]),"r"(r[11]),"r"(r[12]),"r"(r[13]),"r"(r[14]),"r"(r[15])
        : "memory");
}
__device__ __forceinline__ void ldtm16(unsigned* r, unsigned t) {
    asm volatile("tcgen05.ld.sync.aligned.32x32b.x16.b32 "
        "{%0,%1,%2,%3,%4,%5,%6,%7,%8,%9,%10,%11,%12,%13,%14,%15}, [%16];"
        : "=r"(r[0]),"=r"(r[1]),"=r"(r[2]),"=r"(r[3]),"=r"(r[4]),"=r"(r[5]),"=r"(r[6]),"=r"(r[7]),
          "=r"(r[8]),"=r"(r[9]),"=r"(r[10]),"=r"(r[11]),"=r"(r[12]),"=r"(r[13]),"=r"(r[14]),"=r"(r[15])
        : "r"(t));
}
__device__ __forceinline__ void mbar_wait(unsigned mbar, unsigned parity) {
    asm volatile(
        "{ .reg .pred P1;\n\t"
        "W_%=: mbarrier.try_wait.parity.acquire.cta.shared::cta.b64 P1, [%0], %1, 0x989680;\n\t"
        "@P1 bra.uni D_%=;\n\t"
        "bra.uni W_%=;\n\t"
        "D_%=: }" :: "r"(mbar), "r"(parity) : "memory");
}

// 96 MMAs (4 blocks x 6 plane terms small->large x 4 k-steps) + commit
__device__ __forceinline__ void issue_mma_all(unsigned tmem_base, unsigned xbase, unsigned mbar_addr) {
    ull bd[3];
    #pragma unroll
    for (int p = 0; p < 3; p++)
        bd[p] = DESC_BASE | ((ull)((xbase + p * 4096) >> 4) & 0x3FFFULL);
    const int pw[6] = {2, 1, 0, 1, 0, 0};
    const int px[6] = {0, 1, 2, 0, 1, 0};
    #pragma unroll
    for (int L = 0; L < 4; L++) {
        unsigned dT = tmem_base + 384 + L * 32;
        unsigned first = 1;
        #pragma unroll
        for (int t = 0; t < 6; t++) {
            unsigned aT = tmem_base + (L * 3 + pw[t]) * 32;
            #pragma unroll
            for (int kk = 0; kk < 4; kk++) {
                mma_ts(dT, aT + kk * 8, bd[px[t]] + kk * 2, first ? 0u : 1u);
                first = 0;
            }
        }
    }
    asm volatile("tcgen05.commit.cta_group::1.mbarrier::arrive::one.shared::cluster.b64 [%0];"
                 :: "r"(mbar_addr) : "memory");
}

// exact 3-way bf16 split of one float2 of x -> 3 plane words (SW128)
__device__ __forceinline__ void stage_x_planes(char* smemb, unsigned xbyte, int tid, float2 xc) {
    int r = tid >> 5, u = tid & 31;
    unsigned off = sw128((unsigned)(r * 128 + u * 4));
    float a0 = bff(xc.x), b0 = bff(xc.y);
    float ra1 = xc.x - a0, rb1 = xc.y - b0;
    float a1 = bff(ra1), b1 = bff(rb1);
    float ra2 = ra1 - a1, rb2 = rb1 - b1;
    *reinterpret_cast<unsigned*>(smemb + xbyte + off)        = ((unsigned)bfb(xc.y) << 16) | bfb(xc.x);
    *reinterpret_cast<unsigned*>(smemb + xbyte + 4096 + off) = ((unsigned)bfb(rb1) << 16) | bfb(ra1);
    *reinterpret_cast<unsigned*>(smemb + xbyte + 8192 + off) = ((unsigned)bfb(rb2) << 16) | bfb(ra2);
}
#endif

// ---------------- SMEM layouts (float offsets) ----------------
#define T_DECT 0
#define T_XPL  32768                    // 2 buffers x 3 planes x 1024 floats
#define T_ZSH  38912                    // 32*516
#define T_ZSEL 55424                    // 32*32 ull
#define T_CTRL 57472
#define F_DECT 0
#define F_ZSH  32768
#define F_XS   49152
#define F_ZSEL 53248

#define SHMEM_BYTES 229920

__global__ void __launch_bounds__(NTHREADS, 1) __cluster_dims__(1, 1, 1)
sae_kernel(const float* __restrict__ x,
           const float* __restrict__ encW,
           const float* __restrict__ encb,
           const float* __restrict__ decW,
           const float* __restrict__ decb,
           float* __restrict__ outx,
           float* __restrict__ outz,
           int nChunks)
{
    extern __shared__ float smem[];
    const int tid  = threadIdx.x;
    const int lane = tid & 31;
    const int wid  = tid >> 5;
    const unsigned ltmask = (1u << lane) - 1u;
    unsigned Tprev = 0u;

#if defined(HAVE_TCGEN05)
    // ===== tcgen05 path: 32 warps, TMEM ops in warps 0-3, pipelined MMA, split barrier =====
    float* decT = smem + T_DECT;
    float* zsh  = smem + T_ZSH;
    ull*   zsel = reinterpret_cast<ull*>(smem + T_ZSEL);
    char*  smemb = reinterpret_cast<char*>(smem);
    const unsigned smem_base = smem_u32(smem);
    const unsigned ctrl_addr = smem_base + T_CTRL * 4;
    const unsigned mbar_addr = ctrl_addr + 8;
    const unsigned xpl_byte  = T_XPL * 4;

    if (wid == 0) {
        asm volatile("tcgen05.alloc.cta_group::1.sync.aligned.shared::cta.b32 [%0], %1;"
                     :: "r"(ctrl_addr), "r"(512u) : "memory");
    }
    if (tid == 0)
        asm volatile("mbarrier.init.shared.b64 [%0], %1;" :: "r"(mbar_addr), "r"(1u) : "memory");
    __syncthreads();
    unsigned tmem_base;
    asm volatile("ld.shared.b32 %0, [%1];" : "=r"(tmem_base) : "r"(ctrl_addr));

    for (int i = tid; i < D_IN * LATENT; i += NTHREADS) {
        int d = i >> 9, l = i & (LATENT - 1);
        decT[l * DEC_STRIDE + d] = decW[i];
    }

    // W -> 3 exact bf16 planes in TMEM; warps 0-3 only
    float bias4[4] = {0.f, 0.f, 0.f, 0.f};
    if (wid < 4) {
        const unsigned warp_off = ((unsigned)wid) << 21;
        #pragma unroll
        for (int L = 0; L < 4; L++) {
            const int latL = 128 * L + 32 * wid + lane;
            bias4[L] = encb[latL];
            #pragma unroll
            for (int half = 0; half < 2; half++) {
                unsigned r0[16], r1[16], r2[16];
                const float2* wr = reinterpret_cast<const float2*>(encW + latL * D_IN) + half * 16;
                #pragma unroll
                for (int g = 0; g < 16; g++) {
                    float2 v = wr[g];
                    float a0 = bff(v.x), b0 = bff(v.y);
                    float ra1 = v.x - a0, rb1 = v.y - b0;
                    float a1 = bff(ra1), b1 = bff(rb1);
                    float ra2 = ra1 - a1, rb2 = rb1 - b1;
                    r0[g] = ((unsigned)bfb(v.y) << 16) | bfb(v.x);
                    r1[g] = ((unsigned)bfb(rb1) << 16) | bfb(ra1);
                    r2[g] = ((unsigned)bfb(rb2) << 16) | bfb(ra2);
                }
                sttm16(tmem_base + (L * 3 + 0) * 32 + half * 16 + warp_off, r0);
                sttm16(tmem_base + (L * 3 + 1) * 32 + half * 16 + warp_off, r1);
                sttm16(tmem_base + (L * 3 + 2) * 32 + half * 16 + warp_off, r2);
            }
        }
        asm volatile("tcgen05.wait::st.sync.aligned;" ::: "memory");
        asm volatile("tcgen05.fence::before_thread_sync;" ::: "memory");
    }

    const float db0 = decb[2 * lane];
    const float db1 = decb[2 * lane + 1];

    const int c0 = blockIdx.x;
    unsigned parity = 0u;
    int buf = 0;
    const float2* xg2 = reinterpret_cast<const float2*>(x);

    // preloop: stage x(c0) into xpl[0], preload x(c0+GRID), issue MMA(c0)
    if (c0 < nChunks) {
        float2 xc = xg2[(long long)c0 * 1024 + tid];
        stage_x_planes(smemb, xpl_byte, tid, xc);
    }
    float2 xcur = make_float2(0.f, 0.f);
    if (c0 + GRID < nChunks) xcur = xg2[(long long)(c0 + GRID) * 1024 + tid];
    asm volatile("fence.proxy.async.shared::cta;" ::: "memory");
    __syncthreads();
    if (wid == 0 && c0 < nChunks) {
        asm volatile("tcgen05.fence::after_thread_sync;" ::: "memory");
        if (elect_one()) issue_mma_all(tmem_base, smem_base + xpl_byte, mbar_addr);
    }

    for (int c = c0; c < nChunks; c += GRID) {
        const long long row0 = (long long)c * CHUNK;
        const int cn = c + GRID;

        // ---- epilogue: warps 0-3 wait MMA(c), drain D -> zsh (bias; relu at read) ----
        if (wid < 4) {
            mbar_wait(mbar_addr, parity);
            asm volatile("tcgen05.fence::after_thread_sync;" ::: "memory");
            #pragma unroll
            for (int L = 0; L < 4; L++) {
                unsigned d0[16], d1[16];
                ldtm16(d0, tmem_base + 384 + L * 32);
                ldtm16(d1, tmem_base + 384 + L * 32 + 16);
                asm volatile("tcgen05.wait::ld.sync.aligned;" ::: "memory");
                const int latL = 128 * L + 32 * wid + lane;
                #pragma unroll
                for (int j = 0; j < 16; j++) {
                    zsh[j * ZSTRIDE + latL]        = __uint_as_float(d0[j]) + bias4[L];
                    zsh[(j + 16) * ZSTRIDE + latL] = __uint_as_float(d1[j]) + bias4[L];
                }
            }
        }
        parity ^= 1u;

        // ---- stage x(c+GRID) into other buffer; prefetch x(c+2*GRID) ----
        if (cn < nChunks) stage_x_planes(smemb, xpl_byte + (buf ^ 1) * 12288, tid, xcur);
        if (cn + GRID < nChunks) xcur = xg2[(long long)(cn + GRID) * 1024 + tid];
        asm volatile("fence.proxy.async.shared::cta;" ::: "memory");
        __syncthreads();   // zsh(c) ready, xpl(next) ready, D fully drained

        // ---- issue MMA(c+GRID): runs concurrently with topk below ----
        if (wid == 0 && cn < nChunks) {
            asm volatile("tcgen05.fence::after_thread_sync;" ::: "memory");
            if (elect_one()) issue_mma_all(tmem_base, smem_base + xpl_byte + (buf ^ 1) * 12288, mbar_addr);
        }

        // ---- load va with relu (the ONLY zsh reads), then split barrier ----
        float va[16];
        load_va_relu(zsh + wid * ZSTRIDE, lane, va);
        if (wid < 4) {
            asm volatile("bar.sync 1, %0;" :: "n"(NTHREADS) : "memory");
        } else {
            asm volatile("bar.arrive 1, %0;" :: "n"(NTHREADS) : "memory");
        }

        topk_rest(va, row0 + wid, lane, ltmask, Tprev,
                  decT, zsel + wid * KSEL, outx, outz, db0, db1);

        buf ^= 1;
    }

    __syncthreads();
    if (tid == 0)
        asm volatile("mbarrier.inval.shared.b64 [%0];" :: "r"(mbar_addr) : "memory");
    __syncthreads();
    if (wid == 0) {
        asm volatile("tcgen05.dealloc.cta_group::1.sync.aligned.b32 %0, %1;"
                     :: "r"(tmem_base), "r"(512u));
    }

#else
    // ===== FFMA fallback (correctness only; the 'a' cubin loads on GB300) =====
    float* decT = smem + F_DECT;
    float* zsh  = smem + F_ZSH;
    float* xs   = smem + F_XS;
    ull*   zsel = reinterpret_cast<ull*>(smem + F_ZSEL);

    for (int i = tid; i < D_IN * LATENT; i += NTHREADS) {
        int d = i >> 9, l = i & (LATENT - 1);
        decT[l * DEC_STRIDE + d] = decW[i];
    }

    ull w2[32];
    if (tid < 512) {
        const float4* wr = reinterpret_cast<const float4*>(encW + tid * D_IN);
        #pragma unroll
        for (int g = 0; g < 16; g++) {
            float4 v = wr[g];
            w2[2 * g]     = pack2(v.x, v.y);
            w2[2 * g + 1] = pack2(v.z, v.w);
        }
    }
    const float bl  = (tid < 512) ? encb[tid] : 0.0f;
    const float db0 = decb[2 * lane];
    const float db1 = decb[2 * lane + 1];

    int c0 = blockIdx.x;
    int buf = 0;
    if (c0 < nChunks) {
        unsigned dst = smem_u32(xs) + tid * 8;
        cp_async8(dst, x + (long long)c0 * (CHUNK * D_IN) + tid * 2);
    }
    asm volatile("cp.async.commit_group;" ::: "memory");

    for (int c = c0; c < nChunks; c += GRID) {
        const long long row0 = (long long)c * CHUNK;
        float* xsA = xs + buf * (CHUNK * D_IN);

        asm volatile("cp.async.wait_group 0;" ::: "memory");
        __syncthreads();

        {
            int cn = c + GRID;
            if (cn < nChunks) {
                unsigned dst = smem_u32(xs + (buf ^ 1) * (CHUNK * D_IN)) + tid * 8;
                cp_async8(dst, x + (long long)cn * (CHUNK * D_IN) + tid * 2);
            }
            asm volatile("cp.async.commit_group;" ::: "memory");
        }

        if (tid < 512) {
            const ulonglong2* xsu = reinterpret_cast<const ulonglong2*>(xsA);
            #pragma unroll
            for (int rb = 0; rb < CHUNK; rb += 4) {
                ull a0 = 0, a1 = 0, a2 = 0, a3 = 0;
                #pragma unroll
                for (int g = 0; g < 16; g++) {
                    ulonglong2 x0 = xsu[(rb + 0) * 16 + g];
                    ulonglong2 x1 = xsu[(rb + 1) * 16 + g];
                    ulonglong2 x2 = xsu[(rb + 2) * 16 + g];
                    ulonglong2 x3 = xsu[(rb + 3) * 16 + g];
                    a0 = fma2(w2[2 * g], x0.x, a0); a0 = fma2(w2[2 * g + 1], x0.y, a0);
                    a1 = fma2(w2[2 * g], x1.x, a1); a1 = fma2(w2[2 * g + 1], x1.y, a1);
                    a2 = fma2(w2[2 * g], x2.x, a2); a2 = fma2(w2[2 * g + 1], x2.y, a2);
                    a3 = fma2(w2[2 * g], x3.x, a3); a3 = fma2(w2[2 * g + 1], x3.y, a3);
                }
                float lo, hi;
                unpack2(a0, lo, hi); zsh[(rb + 0) * LATENT + tid] = lo + hi + bl;
                unpack2(a1, lo, hi); zsh[(rb + 1) * LATENT + tid] = lo + hi + bl;
                unpack2(a2, lo, hi); zsh[(rb + 2) * LATENT + tid] = lo + hi + bl;
                unpack2(a3, lo, hi); zsh[(rb + 3) * LATENT + tid] = lo + hi + bl;
            }
        }
        __syncthreads();

        float va[16];
        load_va_relu(zsh + wid * LATENT, lane, va);
        topk_rest(va, row0 + wid, lane, ltmask, Tprev,
                  decT, zsel + wid * KSEL, outx, outz, db0, db1);
        __syncthreads();

        buf ^= 1;
    }
#endif
}

extern "C" void kernel_launch(void* const* d_in, const int* in_sizes, int n_in,
                              void* d_out, int out_size)
{
    const float* x    = (const float*)d_in[0];
    const float* encW = (const float*)d_in[1];
    const float* encb = (const float*)d_in[2];
    const float* decW = (const float*)d_in[3];
    const float* decb = (const float*)d_in[4];

    const int B = in_sizes[0] / D_IN;
    float* outx = (float*)d_out;
    float* outz = (float*)d_out + (size_t)B * D_IN;

    const int nChunks = B / CHUNK;

    cudaFuncSetAttribute(sae_kernel, cudaFuncAttributeMaxDynamicSharedMemorySize, SHMEM_BYTES);

    sae_kernel<<<GRID, NTHREADS, SHMEM_BYTES>>>(x, encW, encb, decW, decb, outx, outz, nChunks);
}

// round 16
// speedup vs baseline: 1.2200x; 1.2200x over previous
#include <cuda_runtime.h>
#include <cuda_bf16.h>
#include <cstdint>

#define D_IN      64
#define LATENT    512
#define KSEL      32
#define CHUNK     32
#define NTHREADS  1024
#define GRID      152
#define DEC_STRIDE 64
#define ZSTRIDE   516

typedef unsigned long long ull;

// ---------------- common helpers ----------------
__device__ __forceinline__ ull pack2(float lo, float hi) {
    ull r; asm("mov.b64 %0, {%1,%2};" : "=l"(r) : "f"(lo), "f"(hi)); return r;
}
__device__ __forceinline__ void unpack2(ull v, float& lo, float& hi) {
    asm("mov.b64 {%0,%1}, %2;" : "=f"(lo), "=f"(hi) : "l"(v));
}
__device__ __forceinline__ ull fma2(ull a, ull b, ull c) {
    ull d; asm("fma.rn.f32x2 %0, %1, %2, %3;" : "=l"(d) : "l"(a), "l"(b), "l"(c)); return d;
}
__device__ __forceinline__ ull add2(ull a, ull b) {
    ull d; asm("add.rn.f32x2 %0, %1, %2;" : "=l"(d) : "l"(a), "l"(b)); return d;
}
__device__ __forceinline__ unsigned smem_u32(const void* p) {
    unsigned a; asm("{ .reg .u64 t; cvta.to.shared.u64 t, %1; cvt.u32.u64 %0, t; }" : "=r"(a) : "l"(p));
    return a;
}
__device__ __forceinline__ void cp_async8(unsigned dst, const void* src) {
    asm volatile("cp.async.ca.shared.global [%0], [%1], 8;" :: "r"(dst), "l"(src) : "memory");
}
__device__ __forceinline__ unsigned sw128(unsigned b) { return b ^ ((b >> 3) & 0x70); }
__device__ __forceinline__ unsigned short bfb(float f) {
    __nv_bfloat16 b = __float2bfloat16(f);
    return *reinterpret_cast<unsigned short*>(&b);
}
__device__ __forceinline__ float bff(float f) {
    return __bfloat162float(__float2bfloat16(f));
}
__device__ __forceinline__ void load_va(const float* __restrict__ zrow, int lane, float* va) {
    const float4* zr = reinterpret_cast<const float4*>(zrow);
    #pragma unroll
    for (int q = 0; q < 4; q++) {
        float4 t = zr[lane + 32 * q];
        va[4 * q + 0] = t.x; va[4 * q + 1] = t.y;
        va[4 * q + 2] = t.z; va[4 * q + 3] = t.w;
    }
}

// ---------------- top-k + z write + decode on preloaded va (exact, stable ties) ----------------
// zsel entries hold (dec byte offset = latent*256) in hi32, value bits in lo32.
__device__ __forceinline__ void topk_rest(
    const float* va, long long row, int lane, unsigned ltmask,
    unsigned& Tprev, const float* __restrict__ decT, ull* __restrict__ zs,
    float* __restrict__ outx, float* __restrict__ outz, float db0, float db1)
{
    const unsigned FULL = 0xffffffffu;
    const unsigned lane1024 = ((unsigned)lane) << 10;

    float lmx = 0.0f;
    #pragma unroll
    for (int j = 0; j < 16; j++) lmx = fmaxf(lmx, va[j]);
    unsigned mxu = __reduce_max_sync(FULL, __float_as_uint(lmx));

    unsigned T, ge_cnt;
    if (mxu == 0u) {
        T = 0u; ge_cnt = 512u;
    } else {
        unsigned lo = 0u, hi = mxu + 1u;
        unsigned lo_c = 512u, hi_c = 1u;
        unsigned m = Tprev;
        if (m <= lo || m >= hi) m = lo + ((hi - lo) >> 1);
        T = 0u; ge_cnt = 512u;
        while (true) {
            int cgt = 0;
            #pragma unroll
            for (int j = 0; j < 16; j++) cgt += (__float_as_uint(va[j]) >= m);
            cgt = __reduce_add_sync(FULL, cgt);
            if (cgt == KSEL) {
                unsigned tmin = 0xffffffffu;
                #pragma unroll
                for (int j = 0; j < 16; j++) {
                    unsigned u = __float_as_uint(va[j]);
                    if (u >= m) tmin = min(tmin, u);
                }
                T = __reduce_min_sync(FULL, tmin);
                ge_cnt = KSEL;
                break;
            }
            if (cgt > KSEL) { lo = m; lo_c = (unsigned)cgt; }
            else            { hi = m; hi_c = (unsigned)cgt; }
            if (hi - lo <= 1u) { T = lo; ge_cnt = lo_c; break; }
            float fl = __uint_as_float(lo), fh = __uint_as_float(hi);
            float lc = __logf((float)lo_c);
            float hc = __logf((float)max(hi_c, 1u));
            float t  = (lc - 3.4657359f) / fmaxf(lc - hc, 1e-6f);
            float mf = fl + t * (fh - fl);
            unsigned mm = __float_as_uint(mf);
            if (!(mf > fl && mf < fh)) mm = lo + ((hi - lo) >> 1);
            m = mm;
            if (m <= lo) m = lo + 1u;
            if (m >= hi) m = hi - 1u;
        }
        Tprev = T;
    }

    if (ge_cnt == KSEL) {
        {
            float4* oz = reinterpret_cast<float4*>(outz + row * LATENT);
            #pragma unroll
            for (int q = 0; q < 4; q++) {
                float4 o;
                o.x = (__float_as_uint(va[4*q+0]) >= T) ? va[4*q+0] : 0.0f;
                o.y = (__float_as_uint(va[4*q+1]) >= T) ? va[4*q+1] : 0.0f;
                o.z = (__float_as_uint(va[4*q+2]) >= T) ? va[4*q+2] : 0.0f;
                o.w = (__float_as_uint(va[4*q+3]) >= T) ? va[4*q+3] : 0.0f;
                oz[lane + 32 * q] = o;
            }
        }
        unsigned running = 0;
        #pragma unroll
        for (int j = 0; j < 16; j++) {
            unsigned u = __float_as_uint(va[j]);
            bool sel = (u >= T);
            unsigned bal = __ballot_sync(FULL, sel);
            if (sel) {
                int slot = running + __popc(bal & ltmask);
                unsigned off = (unsigned)(((j >> 2) * 128 + (j & 3)) * 256) + lane1024;
                zs[slot] = ((ull)off << 32) | (ull)u;
            }
            running += __popc(bal);
        }
    } else {
        // rare tie path: exact stable ties matching jax.lax.top_k
        unsigned selmask = 0u;
        int gt = 0;
        #pragma unroll
        for (int j = 0; j < 16; j++) gt += (__float_as_uint(va[j]) > T);
        gt = __reduce_add_sync(FULL, gt);
        int need = KSEL - gt;
        int running = 0;
        #pragma unroll
        for (int j = 0; j < 16; j++) {
            unsigned u = __float_as_uint(va[j]);
            bool g = (u > T), e = (u == T);
            unsigned eb = __ballot_sync(FULL, e);
            int rank = running + __popc(eb & ltmask);
            running += __popc(eb);
            if (g || (e && rank < need)) selmask |= 1u << j;
        }
        {
            float4* oz = reinterpret_cast<float4*>(outz + row * LATENT);
            #pragma unroll
            for (int q = 0; q < 4; q++) {
                float4 o;
                o.x = ((selmask >> (4 * q + 0)) & 1u) ? va[4 * q + 0] : 0.0f;
                o.y = ((selmask >> (4 * q + 1)) & 1u) ? va[4 * q + 1] : 0.0f;
                o.z = ((selmask >> (4 * q + 2)) & 1u) ? va[4 * q + 2] : 0.0f;
                o.w = ((selmask >> (4 * q + 3)) & 1u) ? va[4 * q + 3] : 0.0f;
                oz[lane + 32 * q] = o;
            }
        }
        unsigned running2 = 0;
        #pragma unroll
        for (int j = 0; j < 16; j++) {
            bool sel = (selmask >> j) & 1u;
            unsigned bal = __ballot_sync(FULL, sel);
            if (sel) {
                int slot = running2 + __popc(bal & ltmask);
                unsigned off = (unsigned)(((j >> 2) * 128 + (j & 3)) * 256) + lane1024;
                zs[slot] = ((ull)off << 32) | (ull)__float_as_uint(va[j]);
            }
            running2 += __popc(bal);
        }
    }
    __syncwarp();

    const char* decTlane = reinterpret_cast<const char*>(decT) + 8 * lane;
    ull acc0 = pack2(db0, db1), acc1 = 0, acc2 = 0, acc3 = 0;
    #pragma unroll
    for (int s4 = 0; s4 < KSEL; s4 += 4) {
        ulonglong2 p01 = *reinterpret_cast<const ulonglong2*>(zs + s4);
        ulonglong2 p23 = *reinterpret_cast<const ulonglong2*>(zs + s4 + 2);
        {
            float v = __uint_as_float((unsigned)p01.x);
            acc0 = fma2(pack2(v, v), *reinterpret_cast<const ull*>(decTlane + (p01.x >> 32)), acc0);
        }
        {
            float v = __uint_as_float((unsigned)p01.y);
            acc1 = fma2(pack2(v, v), *reinterpret_cast<const ull*>(decTlane + (p01.y >> 32)), acc1);
        }
        {
            float v = __uint_as_float((unsigned)p23.x);
            acc2 = fma2(pack2(v, v), *reinterpret_cast<const ull*>(decTlane + (p23.x >> 32)), acc2);
        }
        {
            float v = __uint_as_float((unsigned)p23.y);
            acc3 = fma2(pack2(v, v), *reinterpret_cast<const ull*>(decTlane + (p23.y >> 32)), acc3);
        }
    }
    acc0 = add2(add2(acc0, acc1), add2(acc2, acc3));
    float o0, o1;
    unpack2(acc0, o0, o1);
    float2 ov; ov.x = o0; ov.y = o1;
    *reinterpret_cast<float2*>(outx + row * D_IN + 2 * lane) = ov;
}

// ---------------- tcgen05 helpers (only in the *a* pass) ----------------
#if defined(__CUDA_ARCH_FEAT_SM103_ALL) || defined(__CUDA_ARCH_FEAT_SM100_ALL)
#define HAVE_TCGEN05 1
#define MMA_IDESC 0x8080490u             // f32 accum, bf16 x bf16, M=128, N=32
#define DESC_BASE 0x4000404000010000ULL  // SW128 K-major, LBO=1, SBO=64, ver=1

__device__ __forceinline__ unsigned elect_one() {
    unsigned p;
    asm volatile("{ .reg .pred p; elect.sync _|p, 0xFFFFFFFF; selp.b32 %0, 1, 0, p; }" : "=r"(p));
    return p;
}
__device__ __forceinline__ void mma_ts(unsigned d_t, unsigned a_t, ull bdesc, unsigned en) {
    asm volatile(
        "{ .reg .pred p; setp.ne.u32 p, %5, 0;\n\t"
        "tcgen05.mma.cta_group::1.kind::f16 [%0], [%1], %2, %3, {%4,%4,%4,%4}, p; }"
        :: "r"(d_t), "r"(a_t), "l"(bdesc), "r"(MMA_IDESC), "r"(0u), "r"(en) : "memory");
}
__device__ __forceinline__ void sttm16(unsigned t, const unsigned* r) {
    asm volatile("tcgen05.st.sync.aligned.32x32b.x16.b32 [%0], "
        "{%1,%2,%3,%4,%5,%6,%7,%8,%9,%10,%11,%12,%13,%14,%15,%16};"
        :: "r"(t),
        "r"(r[0]),"r"(r[1]),"r"(r[2]),"r"(r[3]),"r"(r[4]),"r"(r[5]),"r"(r[6]),"r"(r[7]),
        "r"(r[8]),"r"(r[9]),"r"(r[10]),"r"(r[11]),"r"(r[12]),"r"(r[13]),"r"(r[14]),"r"(r[15])
        : "memory");
}
__device__ __forceinline__ void ldtm16(unsigned* r, unsigned t) {
    asm volatile("tcgen05.ld.sync.aligned.32x32b.x16.b32 "
        "{%0,%1,%2,%3,%4,%5,%6,%7,%8,%9,%10,%11,%12,%13,%14,%15}, [%16];"
        : "=r"(r[0]),"=r"(r[1]),"=r"(r[2]),"=r"(r[3]),"=r"(r[4]),"=r"(r[5]),"=r"(r[6]),"=r"(r[7]),
          "=r"(r[8]),"=r"(r[9]),"=r"(r[10]),"=r"(r[11]),"=r"(r[12]),"=r"(r[13]),"=r"(r[14]),"=r"(r[15])
        : "r"(t));
}
__device__ __forceinline__ void mbar_wait(unsigned mbar, unsigned parity) {
    asm volatile(
        "{ .reg .pred P1;\n\t"
        "W_%=: mbarrier.try_wait.parity.acquire.cta.shared::cta.b64 P1, [%0], %1, 0x989680;\n\t"
        "@P1 bra.uni D_%=;\n\t"
        "bra.uni W_%=;\n\t"
        "D_%=: }" :: "r"(mbar), "r"(parity) : "memory");
}

// 96 MMAs (4 blocks x 6 plane terms small->large x 4 k-steps) + commit
__device__ __forceinline__ void issue_mma_all(unsigned tmem_base, unsigned xbase, unsigned mbar_addr) {
    ull bd[3];
    #pragma unroll
    for (int p = 0; p < 3; p++)
        bd[p] = DESC_BASE | ((ull)((xbase + p * 4096) >> 4) & 0x3FFFULL);
    const int pw[6] = {2, 1, 0, 1, 0, 0};
    const int px[6] = {0, 1, 2, 0, 1, 0};
    #pragma unroll
    for (int L = 0; L < 4; L++) {
        unsigned dT = tmem_base + 384 + L * 32;
        unsigned first = 1;
        #pragma unroll
        for (int t = 0; t < 6; t++) {
            unsigned aT = tmem_base + (L * 3 + pw[t]) * 32;
            #pragma unroll
            for (int kk = 0; kk < 4; kk++) {
                mma_ts(dT, aT + kk * 8, bd[px[t]] + kk * 2, first ? 0u : 1u);
                first = 0;
            }
        }
    }
    asm volatile("tcgen05.commit.cta_group::1.mbarrier::arrive::one.shared::cluster.b64 [%0];"
                 :: "r"(mbar_addr) : "memory");
}

// exact 3-way bf16 split of one float2 of x -> 3 plane words (SW128)
__device__ __forceinline__ void stage_x_planes(char* smemb, unsigned xbyte, int tid, float2 xc) {
    int r = tid >> 5, u = tid & 31;
    unsigned off = sw128((unsigned)(r * 128 + u * 4));
    float a0 = bff(xc.x), b0 = bff(xc.y);
    float ra1 = xc.x - a0, rb1 = xc.y - b0;
    float a1 = bff(ra1), b1 = bff(rb1);
    float ra2 = ra1 - a1, rb2 = rb1 - b1;
    *reinterpret_cast<unsigned*>(smemb + xbyte + off)        = ((unsigned)bfb(xc.y) << 16) | bfb(xc.x);
    *reinterpret_cast<unsigned*>(smemb + xbyte + 4096 + off) = ((unsigned)bfb(rb1) << 16) | bfb(ra1);
    *reinterpret_cast<unsigned*>(smemb + xbyte + 8192 + off) = ((unsigned)bfb(rb2) << 16) | bfb(ra2);
}
#endif

// ---------------- SMEM layouts (float offsets) ----------------
#define T_DECT 0
#define T_XPL  32768                    // 2 buffers x 3 planes x 1024 floats
#define T_ZSH  38912                    // 32*516
#define T_ZSEL 55424                    // 32*32 ull
#define T_CTRL 57472
#define F_DECT 0
#define F_ZSH  32768
#define F_XS   49152
#define F_ZSEL 53248

#define SHMEM_BYTES 229920

__global__ void __launch_bounds__(NTHREADS, 1) __cluster_dims__(1, 1, 1)
sae_kernel(const float* __restrict__ x,
           const float* __restrict__ encW,
           const float* __restrict__ encb,
           const float* __restrict__ decW,
           const float* __restrict__ decb,
           float* __restrict__ outx,
           float* __restrict__ outz,
           int nChunks)
{
    extern __shared__ float smem[];
    const int tid  = threadIdx.x;
    const int lane = tid & 31;
    const int wid  = tid >> 5;
    const unsigned ltmask = (1u << lane) - 1u;
    unsigned Tprev = 0u;

#if defined(HAVE_TCGEN05)
    // ===== tcgen05 path: 32 warps, TMEM ops in warps 0-3, pipelined MMA, split barrier =====
    float* decT = smem + T_DECT;
    float* zsh  = smem + T_ZSH;
    ull*   zsel = reinterpret_cast<ull*>(smem + T_ZSEL);
    char*  smemb = reinterpret_cast<char*>(smem);
    const unsigned smem_base = smem_u32(smem);
    const unsigned ctrl_addr = smem_base + T_CTRL * 4;
    const unsigned mbar_addr = ctrl_addr + 8;
    const unsigned xpl_byte  = T_XPL * 4;

    if (wid == 0) {
        asm volatile("tcgen05.alloc.cta_group::1.sync.aligned.shared::cta.b32 [%0], %1;"
                     :: "r"(ctrl_addr), "r"(512u) : "memory");
    }
    if (tid == 0)
        asm volatile("mbarrier.init.shared.b64 [%0], %1;" :: "r"(mbar_addr), "r"(1u) : "memory");
    __syncthreads();
    unsigned tmem_base;
    asm volatile("ld.shared.b32 %0, [%1];" : "=r"(tmem_base) : "r"(ctrl_addr));

    for (int i = tid; i < D_IN * LATENT; i += NTHREADS) {
        int d = i >> 9, l = i & (LATENT - 1);
        decT[l * DEC_STRIDE + d] = decW[i];
    }

    // W -> 3 exact bf16 planes in TMEM; warps 0-3 only
    float bias4[4] = {0.f, 0.f, 0.f, 0.f};
    if (wid < 4) {
        const unsigned warp_off = ((unsigned)wid) << 21;
        #pragma unroll
        for (int L = 0; L < 4; L++) {
            const int latL = 128 * L + 32 * wid + lane;
            bias4[L] = encb[latL];
            #pragma unroll
            for (int half = 0; half < 2; half++) {
                unsigned r0[16], r1[16], r2[16];
                const float2* wr = reinterpret_cast<const float2*>(encW + latL * D_IN) + half * 16;
                #pragma unroll
                for (int g = 0; g < 16; g++) {
                    float2 v = wr[g];
                    float a0 = bff(v.x), b0 = bff(v.y);
                    float ra1 = v.x - a0, rb1 = v.y - b0;
                    float a1 = bff(ra1), b1 = bff(rb1);
                    float ra2 = ra1 - a1, rb2 = rb1 - b1;
                    r0[g] = ((unsigned)bfb(v.y) << 16) | bfb(v.x);
                    r1[g] = ((unsigned)bfb(rb1) << 16) | bfb(ra1);
                    r2[g] = ((unsigned)bfb(rb2) << 16) | bfb(ra2);
                }
                sttm16(tmem_base + (L * 3 + 0) * 32 + half * 16 + warp_off, r0);
                sttm16(tmem_base + (L * 3 + 1) * 32 + half * 16 + warp_off, r1);
                sttm16(tmem_base + (L * 3 + 2) * 32 + half * 16 + warp_off, r2);
            }
        }
        asm volatile("tcgen05.wait::st.sync.aligned;" ::: "memory");
        asm volatile("tcgen05.fence::before_thread_sync;" ::: "memory");
    }

    const float db0 = decb[2 * lane];
    const float db1 = decb[2 * lane + 1];

    const int c0 = blockIdx.x;
    unsigned parity = 0u;
    int buf = 0;
    const float2* xg2 = reinterpret_cast<const float2*>(x);

    // preloop: stage x(c0) into xpl[0], preload x(c0+GRID), issue MMA(c0)
    if (c0 < nChunks) {
        float2 xc = xg2[(long long)c0 * 1024 + tid];
        stage_x_planes(smemb, xpl_byte, tid, xc);
    }
    float2 xcur = make_float2(0.f, 0.f);
    if (c0 + GRID < nChunks) xcur = xg2[(long long)(c0 + GRID) * 1024 + tid];
    asm volatile("fence.proxy.async.shared::cta;" ::: "memory");
    __syncthreads();
    if (wid == 0 && c0 < nChunks) {
        asm volatile("tcgen05.fence::after_thread_sync;" ::: "memory");
        if (elect_one()) issue_mma_all(tmem_base, smem_base + xpl_byte, mbar_addr);
    }

    for (int c = c0; c < nChunks; c += GRID) {
        const long long row0 = (long long)c * CHUNK;
        const int cn = c + GRID;

        // ---- epilogue: warps 0-3 wait MMA(c), drain D -> zsh (bias+relu) ----
        if (wid < 4) {
            mbar_wait(mbar_addr, parity);
            asm volatile("tcgen05.fence::after_thread_sync;" ::: "memory");
            #pragma unroll
            for (int L = 0; L < 4; L++) {
                unsigned d0[16], d1[16];
                ldtm16(d0, tmem_base + 384 + L * 32);
                ldtm16(d1, tmem_base + 384 + L * 32 + 16);
                asm volatile("tcgen05.wait::ld.sync.aligned;" ::: "memory");
                const int latL = 128 * L + 32 * wid + lane;
                #pragma unroll
                for (int j = 0; j < 16; j++) {
                    zsh[j * ZSTRIDE + latL]        = fmaxf(__uint_as_float(d0[j]) + bias4[L], 0.0f);
                    zsh[(j + 16) * ZSTRIDE + latL] = fmaxf(__uint_as_float(d1[j]) + bias4[L], 0.0f);
                }
            }
        }
        parity ^= 1u;

        // ---- stage x(c+GRID) into other buffer; prefetch x(c+2*GRID) ----
        if (cn < nChunks) stage_x_planes(smemb, xpl_byte + (buf ^ 1) * 12288, tid, xcur);
        if (cn + GRID < nChunks) xcur = xg2[(long long)(cn + GRID) * 1024 + tid];
        asm volatile("fence.proxy.async.shared::cta;" ::: "memory");
        __syncthreads();   // zsh(c) ready, xpl(next) ready, D fully drained

        // ---- issue MMA(c+GRID): runs concurrently with topk below ----
        if (wid == 0 && cn < nChunks) {
            asm volatile("tcgen05.fence::after_thread_sync;" ::: "memory");
            if (elect_one()) issue_mma_all(tmem_base, smem_base + xpl_byte + (buf ^ 1) * 12288, mbar_addr);
        }

        // ---- load va (the ONLY zsh reads), then split barrier ----
        float va[16];
        load_va(zsh + wid * ZSTRIDE, lane, va);
        if (wid < 4) {
            asm volatile("bar.sync 1, %0;" :: "n"(NTHREADS) : "memory");
        } else {
            asm volatile("bar.arrive 1, %0;" :: "n"(NTHREADS) : "memory");
        }

        topk_rest(va, row0 + wid, lane, ltmask, Tprev,
                  decT, zsel + wid * KSEL, outx, outz, db0, db1);

        buf ^= 1;
    }

    __syncthreads();
    if (tid == 0)
        asm volatile("mbarrier.inval.shared.b64 [%0];" :: "r"(mbar_addr) : "memory");
    __syncthreads();
    if (wid == 0) {
        asm volatile("tcgen05.dealloc.cta_group::1.sync.aligned.b32 %0, %1;"
                     :: "r"(tmem_base), "r"(512u));
    }

#else
    // ===== FFMA fallback (correctness only; the 'a' cubin loads on GB300) =====
    float* decT = smem + F_DECT;
    float* zsh  = smem + F_ZSH;
    float* xs   = smem + F_XS;
    ull*   zsel = reinterpret_cast<ull*>(smem + F_ZSEL);

    for (int i = tid; i < D_IN * LATENT; i += NTHREADS) {
        int d = i >> 9, l = i & (LATENT - 1);
        decT[l * DEC_STRIDE + d] = decW[i];
    }

    ull w2[32];
    if (tid < 512) {
        const float4* wr = reinterpret_cast<const float4*>(encW + tid * D_IN);
        #pragma unroll
        for (int g = 0; g < 16; g++) {
            float4 v = wr[g];
            w2[2 * g]     = pack2(v.x, v.y);
            w2[2 * g + 1] = pack2(v.z, v.w);
        }
    }
    const float bl  = (tid < 512) ? encb[tid] : 0.0f;
    const float db0 = decb[2 * lane];
    const float db1 = decb[2 * lane + 1];

    int c0 = blockIdx.x;
    int buf = 0;
    if (c0 < nChunks) {
        unsigned dst = smem_u32(xs) + tid * 8;
        cp_async8(dst, x + (long long)c0 * (CHUNK * D_IN) + tid * 2);
    }
    asm volatile("cp.async.commit_group;" ::: "memory");

    for (int c = c0; c < nChunks; c += GRID) {
        const long long row0 = (long long)c * CHUNK;
        float* xsA = xs + buf * (CHUNK * D_IN);

        asm volatile("cp.async.wait_group 0;" ::: "memory");
        __syncthreads();

        {
            int cn = c + GRID;
            if (cn < nChunks) {
                unsigned dst = smem_u32(xs + (buf ^ 1) * (CHUNK * D_IN)) + tid * 8;
                cp_async8(dst, x + (long long)cn * (CHUNK * D_IN) + tid * 2);
            }
            asm volatile("cp.async.commit_group;" ::: "memory");
        }

        if (tid < 512) {
            const ulonglong2* xsu = reinterpret_cast<const ulonglong2*>(xsA);
            #pragma unroll
            for (int rb = 0; rb < CHUNK; rb += 4) {
                ull a0 = 0, a1 = 0, a2 = 0, a3 = 0;
                #pragma unroll
                for (int g = 0; g < 16; g++) {
                    ulonglong2 x0 = xsu[(rb + 0) * 16 + g];
                    ulonglong2 x1 = xsu[(rb + 1) * 16 + g];
                    ulonglong2 x2 = xsu[(rb + 2) * 16 + g];
                    ulonglong2 x3 = xsu[(rb + 3) * 16 + g];
                    a0 = fma2(w2[2 * g], x0.x, a0); a0 = fma2(w2[2 * g + 1], x0.y, a0);
                    a1 = fma2(w2[2 * g], x1.x, a1); a1 = fma2(w2[2 * g + 1], x1.y, a1);
                    a2 = fma2(w2[2 * g], x2.x, a2); a2 = fma2(w2[2 * g + 1], x2.y, a2);
                    a3 = fma2(w2[2 * g], x3.x, a3); a3 = fma2(w2[2 * g + 1], x3.y, a3);
                }
                float lo, hi;
                unpack2(a0, lo, hi); zsh[(rb + 0) * LATENT + tid] = fmaxf(lo + hi + bl, 0.0f);
                unpack2(a1, lo, hi); zsh[(rb + 1) * LATENT + tid] = fmaxf(lo + hi + bl, 0.0f);
                unpack2(a2, lo, hi); zsh[(rb + 2) * LATENT + tid] = fmaxf(lo + hi + bl, 0.0f);
                unpack2(a3, lo, hi); zsh[(rb + 3) * LATENT + tid] = fmaxf(lo + hi + bl, 0.0f);
            }
        }
        __syncthreads();

        float va[16];
        load_va(zsh + wid * LATENT, lane, va);
        topk_rest(va, row0 + wid, lane, ltmask, Tprev,
                  decT, zsel + wid * KSEL, outx, outz, db0, db1);
        __syncthreads();

        buf ^= 1;
    }
#endif
}

extern "C" void kernel_launch(void* const* d_in, const int* in_sizes, int n_in,
                              void* d_out, int out_size)
{
    const float* x    = (const float*)d_in[0];
    const float* encW = (const float*)d_in[1];
    const float* encb = (const float*)d_in[2];
    const float* decW = (const float*)d_in[3];
    const float* decb = (const float*)d_in[4];

    const int B = in_sizes[0] / D_IN;
    float* outx = (float*)d_out;
    float* outz = (float*)d_out + (size_t)B * D_IN;

    const int nChunks = B / CHUNK;

    cudaFuncSetAttribute(sae_kernel, cudaFuncAttributeMaxDynamicSharedMemorySize, SHMEM_BYTES);

    sae_kernel<<<GRID, NTHREADS, SHMEM_BYTES>>>(x, encW, encb, decW, decb, outx, outz, nChunks);
}